// round 12
// baseline (speedup 1.0000x reference)
#include <cuda_runtime.h>
#include <cuda_bf16.h>
#include <math.h>
#include <stdint.h>

#define C_CH   128
#define N_PTS  32768
#define K_PWL  20
#define LATENT 8
#define HID    8
#define NSEG   (K_PWL - 1)

// ---------------- scratch (static device memory; no allocations) ----------------
__device__ float g_x[(size_t)C_CH * N_PTS];     // raw x MLP outputs [C][N]
__device__ float g_e[(size_t)C_CH * N_PTS];     // raw e MLP outputs [C][N]
__device__ float g_slope[C_CH * NSEG];          // per-channel PWL segment slopes
__device__ float g_icept[C_CH * NSEG];          // per-channel PWL segment intercepts
__device__ unsigned int g_minbits[C_CH];
__device__ unsigned int g_maxbits[C_CH];
__device__ float g_minv[C_CH];
__device__ float g_scale[C_CH];
__device__ float g_psum[2048];
__device__ float g_psumsq[2048];
__device__ float g_eA;   // 0.1 * invstd
__device__ float g_eB;   // -0.1 * mean * invstd
__device__ unsigned int g_done;  // zero-init; reset by finalize each run

// xp = linspace(0,1,20) in f32
#define XPV(k) ((float)((double)(k) / 19.0))
__constant__ float c_xp[K_PWL] = {
    XPV(0), XPV(1), XPV(2), XPV(3), XPV(4), XPV(5), XPV(6), XPV(7), XPV(8), XPV(9),
    XPV(10), XPV(11), XPV(12), XPV(13), XPV(14), XPV(15), XPV(16), XPV(17), XPV(18), XPV(19)
};

// ---------------- helpers ----------------
__device__ __forceinline__ unsigned int fenc(float f) {
    unsigned int u = __float_as_uint(f);
    return (u >> 31) ? ~u : (u | 0x80000000u);
}
__device__ __forceinline__ float fdec(unsigned int u) {
    return (u & 0x80000000u) ? __uint_as_float(u & 0x7FFFFFFFu) : __uint_as_float(~u);
}

// Fast, tight-absolute-error tanh: (e^{2x}-1)/(e^{2x}+1). abs err ~1e-7.
__device__ __forceinline__ float tanh_fast(float x) {
    x = fminf(fmaxf(x, -30.0f), 30.0f);
    float t = __expf(2.0f * x);
    return __fdividef(t - 1.0f, t + 1.0f);
}

// ---------------- shared-memory weight block for the pass kernels ----------------
// Layout (floats): [0:64) W1 row-major, [64:72) b1, [72:80) W2, [80] b2.
struct PassSmem {
    float w[84];        // 16B-aligned region for float4 LDS
    float red1[256];
    float red2[256];
};

__device__ __forceinline__ void load_weights_smem(
    float* sw, int tid,
    const float* __restrict__ W1, const float* __restrict__ b1,
    const float* __restrict__ W2, const float* __restrict__ b2) {
    if (tid < 64) sw[tid] = __ldg(W1 + tid);
    else if (tid < 72) sw[tid] = __ldg(b1 + tid - 64);
    else if (tid < 80) sw[tid] = __ldg(W2 + tid - 72);
    else if (tid == 80) sw[tid] = __ldg(b2);
    else if (tid < 84) sw[tid] = 0.0f;
}

// MLP for one point; weights read from smem (float4 LDS, broadcast).
__device__ __forceinline__ float mlp_point_smem(const float* sw, float4 a, float4 bq) {
    const float4* sw4 = reinterpret_cast<const float4*>(sw);
    float4 b1a = sw4[16], b1b = sw4[17];           // b1
    float h0 = b1a.x, h1 = b1a.y, h2 = b1a.z, h3 = b1a.w;
    float h4 = b1b.x, h5 = b1b.y, h6 = b1b.z, h7 = b1b.w;
    float z[8] = {a.x, a.y, a.z, a.w, bq.x, bq.y, bq.z, bq.w};
#pragma unroll
    for (int i = 0; i < 8; i++) {
        float zi = z[i];
        float4 wA = sw4[i * 2 + 0];
        float4 wB = sw4[i * 2 + 1];
        h0 = fmaf(zi, wA.x, h0); h1 = fmaf(zi, wA.y, h1);
        h2 = fmaf(zi, wA.z, h2); h3 = fmaf(zi, wA.w, h3);
        h4 = fmaf(zi, wB.x, h4); h5 = fmaf(zi, wB.y, h5);
        h6 = fmaf(zi, wB.z, h6); h7 = fmaf(zi, wB.w, h7);
    }
    float4 w2a = sw4[18], w2b = sw4[19];           // W2
    float o = sw[80];                              // b2
    o = fmaf(tanh_fast(h0), w2a.x, o);
    o = fmaf(tanh_fast(h1), w2a.y, o);
    o = fmaf(tanh_fast(h2), w2a.z, o);
    o = fmaf(tanh_fast(h3), w2a.w, o);
    o = fmaf(tanh_fast(h4), w2b.x, o);
    o = fmaf(tanh_fast(h5), w2b.y, o);
    o = fmaf(tanh_fast(h6), w2b.z, o);
    o = fmaf(tanh_fast(h7), w2b.w, o);
    return tanh_fast(o);
}

// ---------------- K1: PWL generator (tiny) + slope/intercept tables + init ----------------
__global__ void gen_pwl_kernel(const float* __restrict__ zf,
                               const float* __restrict__ Wf1, const float* __restrict__ bf1,
                               const float* __restrict__ Wf2, const float* __restrict__ bf2,
                               const void* __restrict__ dirs_raw) {
    int c = threadIdx.x;  // 128 threads, one per channel
    // Parallel dtype detection for `directions`:
    //   bit0 -> some byte at offset %4 != 0 is nonzero  (NOT int32 0/1)
    //   bit1 -> some byte value > 1                     (NOT a 0/1 byte array)
    __shared__ unsigned int flags;
    if (c == 0) { flags = 0u; g_done = 0u; }
    __syncthreads();
    {
        unsigned char v = ((const unsigned char*)dirs_raw)[c];
        unsigned int f = 0u;
        if ((c & 3) != 0 && v != 0) f |= 1u;
        if (v > 1) f |= 2u;
        if (f) atomicOr(&flags, f);
    }
    __syncthreads();
    // mode: 0 = int32, 1 = uint8/bool, 2 = float32
    const int mode = (!(flags & 1u)) ? 0 : ((!(flags & 2u)) ? 1 : 2);

    float z[LATENT];
#pragma unroll
    for (int i = 0; i < LATENT; i++) z[i] = zf[c * LATENT + i];

    float h[HID];
#pragma unroll
    for (int j = 0; j < HID; j++) h[j] = bf1[j];
#pragma unroll
    for (int i = 0; i < LATENT; i++)
#pragma unroll
        for (int j = 0; j < HID; j++) h[j] = fmaf(z[i], Wf1[i * HID + j], h[j]);
#pragma unroll
    for (int j = 0; j < HID; j++) h[j] = tanh_fast(h[j]);

    float pts[K_PWL];
#pragma unroll
    for (int k = 0; k < K_PWL; k++) {
        float s = bf2[k];
#pragma unroll
        for (int j = 0; j < HID; j++) s = fmaf(h[j], Wf2[j * K_PWL + k], s);
        pts[k] = tanh_fast(s);
    }
    // insertion sort ascending
    for (int a = 1; a < K_PWL; a++) {
        float v = pts[a];
        int b = a - 1;
        while (b >= 0 && pts[b] > v) { pts[b + 1] = pts[b]; b--; }
        pts[b + 1] = v;
    }
    bool dir;
    if (mode == 0)      dir = ((const int*)dirs_raw)[c] != 0;
    else if (mode == 1) dir = ((const unsigned char*)dirs_raw)[c] != 0;
    else                dir = ((const float*)dirs_raw)[c] > 0.5f;

    // Per-segment slope/intercept: y(xv) = sl*xv + ic on [xp[k], xp[k+1]]
    for (int k = 0; k < NSEG; k++) {
        float y0 = dir ? pts[k]     : pts[K_PWL - 1 - k];
        float y1 = dir ? pts[k + 1] : pts[K_PWL - 2 - k];
        float sl = (y1 - y0) / (c_xp[k + 1] - c_xp[k] + 1e-7f);
        g_slope[c * NSEG + k] = sl;
        g_icept[c * NSEG + k] = fmaf(-c_xp[k], sl, y0);
    }

    g_minbits[c] = 0xFFFFFFFFu;
    g_maxbits[c] = 0u;
}

// ---------------- K2: x MLP + per-channel min/max (software-pipelined) ----------------
// 4 iterations x 2 points per thread; next iteration's 4 float4 loads are
// issued before computing the current pair -> 4-8 independent LDGs in flight.
__global__ void __launch_bounds__(256, 4) pass_x_kernel(
    const float* __restrict__ zx,
    const float* __restrict__ W1, const float* __restrict__ b1,
    const float* __restrict__ W2, const float* __restrict__ b2) {
    __shared__ PassSmem sm;
    const int tid = threadIdx.x;
    load_weights_smem(sm.w, tid, W1, b1, W2, b2);
    __syncthreads();

    const int c = blockIdx.y;
    const size_t base = (size_t)c * N_PTS;
    const int n0 = blockIdx.x * 2048;
    const float4* __restrict__ src4 = reinterpret_cast<const float4*>(zx + base * LATENT);

    float lmin = 1e30f, lmax = -1e30f;

    int n = n0 + tid;
    float4 ca0 = src4[2 * n],         cb0 = src4[2 * n + 1];
    float4 ca1 = src4[2 * (n + 256)], cb1 = src4[2 * (n + 256) + 1];
#pragma unroll
    for (int k = 0; k < 4; k++) {
        float4 na0, nb0, na1, nb1;
        if (k < 3) {
            int nn = n0 + (k + 1) * 512 + tid;
            na0 = src4[2 * nn];         nb0 = src4[2 * nn + 1];
            na1 = src4[2 * (nn + 256)]; nb1 = src4[2 * (nn + 256) + 1];
        }
        int ncur = n0 + k * 512 + tid;
        float v0 = mlp_point_smem(sm.w, ca0, cb0);
        float v1 = mlp_point_smem(sm.w, ca1, cb1);
        g_x[base + ncur] = v0;
        g_x[base + ncur + 256] = v1;
        lmin = fminf(lmin, fminf(v0, v1));
        lmax = fmaxf(lmax, fmaxf(v0, v1));
        ca0 = na0; cb0 = nb0; ca1 = na1; cb1 = nb1;
    }

    sm.red1[tid] = lmin; sm.red2[tid] = lmax; __syncthreads();
    for (int s = 128; s; s >>= 1) {
        if (tid < s) {
            sm.red1[tid] = fminf(sm.red1[tid], sm.red1[tid + s]);
            sm.red2[tid] = fmaxf(sm.red2[tid], sm.red2[tid + s]);
        }
        __syncthreads();
    }
    if (tid == 0) {
        atomicMin(&g_minbits[c], fenc(sm.red1[0]));
        atomicMax(&g_maxbits[c], fenc(sm.red2[0]));
    }
}

// ---------------- K3: e MLP + partials + last-block finalize (software-pipelined) ----------------
__global__ void __launch_bounds__(256, 4) pass_e_kernel(
    const float* __restrict__ ze,
    const float* __restrict__ W1, const float* __restrict__ b1,
    const float* __restrict__ W2, const float* __restrict__ b2) {
    __shared__ PassSmem sm;
    const int tid = threadIdx.x;
    load_weights_smem(sm.w, tid, W1, b1, W2, b2);
    __syncthreads();

    const int c = blockIdx.y;
    const size_t base = (size_t)c * N_PTS;
    const int n0 = blockIdx.x * 2048;
    const float4* __restrict__ src4 = reinterpret_cast<const float4*>(ze + base * LATENT);

    float ls = 0.0f, lq = 0.0f;

    int n = n0 + tid;
    float4 ca0 = src4[2 * n],         cb0 = src4[2 * n + 1];
    float4 ca1 = src4[2 * (n + 256)], cb1 = src4[2 * (n + 256) + 1];
#pragma unroll
    for (int k = 0; k < 4; k++) {
        float4 na0, nb0, na1, nb1;
        if (k < 3) {
            int nn = n0 + (k + 1) * 512 + tid;
            na0 = src4[2 * nn];         nb0 = src4[2 * nn + 1];
            na1 = src4[2 * (nn + 256)]; nb1 = src4[2 * (nn + 256) + 1];
        }
        int ncur = n0 + k * 512 + tid;
        float v0 = mlp_point_smem(sm.w, ca0, cb0);
        float v1 = mlp_point_smem(sm.w, ca1, cb1);
        g_e[base + ncur] = v0;
        g_e[base + ncur + 256] = v1;
        ls += v0; lq = fmaf(v0, v0, lq);
        ls += v1; lq = fmaf(v1, v1, lq);
        ca0 = na0; cb0 = nb0; ca1 = na1; cb1 = nb1;
    }

    __shared__ bool amLast;
    sm.red1[tid] = ls; sm.red2[tid] = lq; __syncthreads();
    for (int s = 128; s; s >>= 1) {
        if (tid < s) { sm.red1[tid] += sm.red1[tid + s]; sm.red2[tid] += sm.red2[tid + s]; }
        __syncthreads();
    }
    if (tid == 0) {
        int pid = blockIdx.y * gridDim.x + blockIdx.x;
        g_psum[pid] = sm.red1[0];
        g_psumsq[pid] = sm.red2[0];
        __threadfence();                       // release partials
        unsigned int t = atomicAdd(&g_done, 1u);
        amLast = (t == 2048u - 1u);
    }
    __syncthreads();

    // Last block performs the deterministic fixed-order fp64 reduce.
    if (amLast) {
        __threadfence();                       // acquire all partials
        double s = 0.0, q = 0.0;
#pragma unroll
        for (int i = 0; i < 8; i++) {
            int idx = tid + i * 256;
            s += (double)g_psum[idx];
            q += (double)g_psumsq[idx];
        }
        double* sds = reinterpret_cast<double*>(sm.red1);  // 2KB: 256 doubles
        sds[tid] = s; __syncthreads();
        for (int k = 128; k; k >>= 1) {
            if (tid < k) sds[tid] += sds[tid + k];
            __syncthreads();
        }
        double stot = sds[0]; __syncthreads();
        sds[tid] = q; __syncthreads();
        for (int k = 128; k; k >>= 1) {
            if (tid < k) sds[tid] += sds[tid + k];
            __syncthreads();
        }
        double qtot = sds[0];
        if (tid == 0) {
            double CN = (double)C_CH * (double)N_PTS;
            double mean = stot / CN;
            double var = (qtot - stot * stot / CN) / (CN - 1.0);
            double invstd = 1.0 / sqrt(var);
            g_eA = (float)(0.1 * invstd);
            g_eB = (float)(-0.1 * mean * invstd);
            g_done = 0u;                       // reset for next graph replay
        }
        if (tid < C_CH) {
            float mn = fdec(g_minbits[tid]);   // pass_x completed before this kernel (stream order)
            float mx = fdec(g_maxbits[tid]);
            g_minv[tid] = mn;
            g_scale[tid] = 1.0f / (mx - mn);
        }
        __threadfence();
    }
}

// ---------------- K4: transpose + direct-index PWL + noise (double-buffered) ----------------
// Block covers 32 channels x 128 n (4 sub-tiles of 32x32, pipelined).
__global__ void __launch_bounds__(256) out_kernel(float* __restrict__ out) {
    __shared__ float sx[2][32][33];
    __shared__ float se[2][32][33];
    __shared__ float ssl[32][NSEG + 1];
    __shared__ float ssb[32][NSEG + 1];
    __shared__ float smn[32];
    __shared__ float ssc[32];

    const int tx = threadIdx.x, ty = threadIdx.y;
    const int tid = ty * 32 + tx;
    const int nb = blockIdx.x * 128;
    const int c0 = blockIdx.y * 32;

    for (int idx = tid; idx < 32 * NSEG; idx += 256) {
        int cl = idx / NSEG, k = idx % NSEG;
        ssl[cl][k] = g_slope[(c0 + cl) * NSEG + k];
        ssb[cl][k] = g_icept[(c0 + cl) * NSEG + k];
    }
    if (tid < 32) {
        smn[tid] = g_minv[c0 + tid];
        ssc[tid] = g_scale[c0 + tid];
    }
    const float eA = g_eA, eB = g_eB;

    // Preload tile 0
    float rx[4], re[4];
#pragma unroll
    for (int r = 0; r < 4; r++) {
        int cl = ty + r * 8;
        size_t off = (size_t)(c0 + cl) * N_PTS + nb + tx;
        rx[r] = g_x[off];
        re[r] = g_e[off];
    }
#pragma unroll
    for (int r = 0; r < 4; r++) {
        int cl = ty + r * 8;
        sx[0][cl][tx] = rx[r];
        se[0][cl][tx] = re[r];
    }
    __syncthreads();

    const float mn = smn[tx], sc = ssc[tx];

#pragma unroll
    for (int t = 0; t < 4; t++) {
        const int cur = t & 1;
        // Issue next tile's loads (latency overlaps compute below)
        if (t < 3) {
            const int n1 = nb + (t + 1) * 32;
#pragma unroll
            for (int r = 0; r < 4; r++) {
                int cl = ty + r * 8;
                size_t off = (size_t)(c0 + cl) * N_PTS + n1 + tx;
                rx[r] = g_x[off];
                re[r] = g_e[off];
            }
        }
        // Compute current tile from smem
        const int n0 = nb + t * 32;
#pragma unroll
        for (int r = 0; r < 4; r++) {
            int nn = ty + r * 8;
            float xv = (sx[cur][tx][nn] - mn) * sc;
            int j = min(max(__float2int_rd(xv * 19.0f), 0), NSEG - 1);
            float y = fmaf(xv, ssl[tx][j], ssb[tx][j]);
            out[(size_t)(n0 + nn) * C_CH + c0 + tx] = fmaf(se[cur][tx][nn], eA, y + eB);
        }
        if (t < 3) {
            __syncthreads();   // everyone done reading buf (t+1)&1 from 2 tiles ago
            const int nxt = (t + 1) & 1;
#pragma unroll
            for (int r = 0; r < 4; r++) {
                int cl = ty + r * 8;
                sx[nxt][cl][tx] = rx[r];
                se[nxt][cl][tx] = re[r];
            }
            __syncthreads();
        }
    }
}

// ---------------- launch ----------------
extern "C" void kernel_launch(void* const* d_in, const int* in_sizes, int n_in,
                              void* d_out, int out_size) {
    const float* zf  = (const float*)d_in[0];
    const float* zx  = (const float*)d_in[1];
    const float* ze  = (const float*)d_in[2];
    const float* Wx1 = (const float*)d_in[3];
    const float* bx1 = (const float*)d_in[4];
    const float* Wx2 = (const float*)d_in[5];
    const float* bx2 = (const float*)d_in[6];
    const float* We1 = (const float*)d_in[7];
    const float* be1 = (const float*)d_in[8];
    const float* We2 = (const float*)d_in[9];
    const float* be2 = (const float*)d_in[10];
    const float* Wf1 = (const float*)d_in[11];
    const float* bf1 = (const float*)d_in[12];
    const float* Wf2 = (const float*)d_in[13];
    const float* bf2 = (const float*)d_in[14];
    const void*  dirs = d_in[15];
    float* out = (float*)d_out;

    gen_pwl_kernel<<<1, 128>>>(zf, Wf1, bf1, Wf2, bf2, dirs);
    pass_x_kernel<<<dim3(16, 128), 256>>>(zx, Wx1, bx1, Wx2, bx2);
    pass_e_kernel<<<dim3(16, 128), 256>>>(ze, We1, be1, We2, be2);
    out_kernel<<<dim3(N_PTS / 128, C_CH / 32), dim3(32, 8)>>>(out);
}